// round 2
// baseline (speedup 1.0000x reference)
#include <cuda_runtime.h>
#include <cuda_bf16.h>

// ---------------- problem constants ----------------
#define NPAT   16
#define BB     16
#define CC     16
#define HH     256
#define PH     16
#define PP     256          // patches per image
#define DD     4096         // C*ph*pw
#define EE     512
#define ROWS   (BB*PP)      // 4096 patch rows total
#define TAU    1e-7f

// ---------------- device scratch ----------------
__device__ float d_p[ROWS * DD];        // 64 MiB  patches fp32
__device__ float d_gwT[DD * DD];        // 64 MiB  g_w transposed
__device__ float d_theta[ROWS * EE];    // 8 MiB
__device__ float d_f[ROWS * EE];        // 8 MiB
__device__ float d_logits[BB * PP * PP];// 4 MiB
__device__ int   d_sig_n[ROWS * PP];    // significant column indices
__device__ float d_sig_w[ROWS * PP];    // their softmax weights
__device__ int   d_cnt[ROWS];

// ---------------- K1: patch extract + out = x ----------------
__global__ __launch_bounds__(256) void extract_kernel(
    const float* __restrict__ x, float* __restrict__ out)
{
    int idx4 = blockIdx.x * 256 + threadIdx.x;      // 4,194,304 total
    int i = idx4 * 4;
    int w = i & 255;
    int h = (i >> 8) & 255;
    int c = (i >> 16) & 15;
    int b = i >> 20;

    float4 v = *(const float4*)(x + i);
    *(float4*)(out + i) = v;                        // out = x everywhere

    int py = h >> 4, iy = h & 15;
    int px = w >> 4, ix = w & 15;                   // ix multiple of 4
    int pidx = py * NPAT + px;
    int d    = c * (PH * PH) + iy * PH + ix;
    *(float4*)(d_p + (size_t)(b * PP + pidx) * DD + d) = v;
}

// ---------------- K2: transpose g_w (D x D) ----------------
__global__ __launch_bounds__(256) void transpose_kernel(const float* __restrict__ gw)
{
    __shared__ float tile[32][33];
    int tx = threadIdx.x, ty = threadIdx.y;         // 32 x 8
    int x0 = blockIdx.x * 32, y0 = blockIdx.y * 32;
#pragma unroll
    for (int j = 0; j < 32; j += 8)
        tile[ty + j][tx] = gw[(size_t)(y0 + ty + j) * DD + (x0 + tx)];
    __syncthreads();
#pragma unroll
    for (int j = 0; j < 32; j += 8)
        d_gwT[(size_t)(x0 + ty + j) * DD + (y0 + tx)] = tile[tx][ty + j];
}

// ---------------- K3: fused fp32 GEMM  {theta,f}[4096x512] = p @ W + bias ----------------
// BM=128 BN=64 BK=16, 256 threads, 8x4 per thread, gridDim.z selects theta/f
__global__ __launch_bounds__(256) void gemm4096(
    const float* __restrict__ W0, const float* __restrict__ b0,
    const float* __restrict__ W1, const float* __restrict__ b1)
{
    int sel = blockIdx.z;
    const float* __restrict__ W    = sel ? W1 : W0;
    const float* __restrict__ bias = sel ? b1 : b0;
    float* C = sel ? d_f : d_theta;

    __shared__ float As[16][128];
    __shared__ float Bs[16][64];

    int t  = threadIdx.x;
    int tx = t & 15;              // N-dir: 16 threads x 4 cols
    int ty = t >> 4;              // M-dir: 16 threads x 8 rows
    int m0 = blockIdx.y * 128, n0 = blockIdx.x * 64;

    int ar = t >> 1;              // 0..127 : A tile row
    int ak = (t & 1) * 8;         // k sub-offset (two float4s: ak, ak+4)
    int br = t >> 4;              // 0..15 : B tile k-row
    int bn = (t & 15) * 4;        // B col

    float acc[8][4];
#pragma unroll
    for (int i = 0; i < 8; i++)
#pragma unroll
        for (int j = 0; j < 4; j++) acc[i][j] = 0.f;

    const float* aptr = d_p + (size_t)(m0 + ar) * DD + ak;

    for (int k0 = 0; k0 < DD; k0 += 16) {
        float4 a0 = *(const float4*)(aptr + k0);
        float4 a1 = *(const float4*)(aptr + k0 + 4);
        As[ak + 0][ar] = a0.x; As[ak + 1][ar] = a0.y;
        As[ak + 2][ar] = a0.z; As[ak + 3][ar] = a0.w;
        As[ak + 4][ar] = a1.x; As[ak + 5][ar] = a1.y;
        As[ak + 6][ar] = a1.z; As[ak + 7][ar] = a1.w;
        *(float4*)&Bs[br][bn] = *(const float4*)(W + (size_t)(k0 + br) * EE + n0 + bn);
        __syncthreads();
#pragma unroll
        for (int kk = 0; kk < 16; kk++) {
            float4 a0v = *(const float4*)&As[kk][ty * 8];
            float4 a1v = *(const float4*)&As[kk][ty * 8 + 4];
            float4 bv  = *(const float4*)&Bs[kk][tx * 4];
            float ra[8] = {a0v.x, a0v.y, a0v.z, a0v.w, a1v.x, a1v.y, a1v.z, a1v.w};
            float rb[4] = {bv.x, bv.y, bv.z, bv.w};
#pragma unroll
            for (int i = 0; i < 8; i++)
#pragma unroll
                for (int j = 0; j < 4; j++) acc[i][j] += ra[i] * rb[j];
        }
        __syncthreads();
    }

    float4 bb = *(const float4*)(bias + n0 + tx * 4);
    float rb[4] = {bb.x, bb.y, bb.z, bb.w};
#pragma unroll
    for (int i = 0; i < 8; i++) {
        int row = m0 + ty * 8 + i;
        float4 o = make_float4(acc[i][0] + rb[0], acc[i][1] + rb[1],
                               acc[i][2] + rb[2], acc[i][3] + rb[3]);
        *(float4*)(C + (size_t)row * EE + n0 + tx * 4) = o;
    }
}

// ---------------- K4: logits  L[b] = theta[b] @ f[b]^T  (256x256, K=512) ----------------
__global__ __launch_bounds__(256) void logits_kernel()
{
    __shared__ float As[16][64];   // As[e][p]
    __shared__ float Bs[16][64];   // Bs[e][q]
    int b  = blockIdx.z;
    int t  = threadIdx.x;
    int tx = t & 15, ty = t >> 4;
    int p0 = blockIdx.y * 64, q0 = blockIdx.x * 64;

    const float* A  = d_theta + (size_t)b * PP * EE;
    const float* Bm = d_f     + (size_t)b * PP * EE;

    int ar = t >> 2;
    int ak = (t & 3) * 4;

    float acc[4][4];
#pragma unroll
    for (int i = 0; i < 4; i++)
#pragma unroll
        for (int j = 0; j < 4; j++) acc[i][j] = 0.f;

    for (int e0 = 0; e0 < EE; e0 += 16) {
        float4 av = *(const float4*)(A  + (size_t)(p0 + ar) * EE + e0 + ak);
        As[ak + 0][ar] = av.x; As[ak + 1][ar] = av.y;
        As[ak + 2][ar] = av.z; As[ak + 3][ar] = av.w;
        float4 bv = *(const float4*)(Bm + (size_t)(q0 + ar) * EE + e0 + ak);
        Bs[ak + 0][ar] = bv.x; Bs[ak + 1][ar] = bv.y;
        Bs[ak + 2][ar] = bv.z; Bs[ak + 3][ar] = bv.w;
        __syncthreads();
#pragma unroll
        for (int kk = 0; kk < 16; kk++) {
            float4 a  = *(const float4*)&As[kk][ty * 4];
            float4 b2 = *(const float4*)&Bs[kk][tx * 4];
            float ra[4] = {a.x, a.y, a.z, a.w};
            float rb[4] = {b2.x, b2.y, b2.z, b2.w};
#pragma unroll
            for (int i = 0; i < 4; i++)
#pragma unroll
                for (int j = 0; j < 4; j++) acc[i][j] += ra[i] * rb[j];
        }
        __syncthreads();
    }
#pragma unroll
    for (int i = 0; i < 4; i++) {
        float4 o = make_float4(acc[i][0], acc[i][1], acc[i][2], acc[i][3]);
        *(float4*)(d_logits + (size_t)b * PP * PP + (size_t)(p0 + ty * 4 + i) * PP
                   + q0 + tx * 4) = o;
    }
}

// ---------------- K5: softmax + tau-compaction, one block per row ----------------
__global__ __launch_bounds__(256) void softmax_kernel()
{
    __shared__ float red[8];
    __shared__ int   cnt;
    int row = blockIdx.x;
    int t = threadIdx.x;
    int lane = t & 31, wid = t >> 5;

    float l = d_logits[(size_t)row * PP + t];

    float m = l;
#pragma unroll
    for (int off = 16; off; off >>= 1)
        m = fmaxf(m, __shfl_down_sync(0xffffffffu, m, off));
    if (lane == 0) red[wid] = m;
    __syncthreads();
    if (t == 0) {
        float mm = red[0];
#pragma unroll
        for (int w = 1; w < 8; w++) mm = fmaxf(mm, red[w]);
        red[0] = mm;
        cnt = 0;
    }
    __syncthreads();
    float mx = red[0];
    __syncthreads();

    float e = expf(l - mx);
    float s = e;
#pragma unroll
    for (int off = 16; off; off >>= 1)
        s += __shfl_down_sync(0xffffffffu, s, off);
    if (lane == 0) red[wid] = s;
    __syncthreads();
    if (t == 0) {
        float ss = 0.f;
#pragma unroll
        for (int w = 0; w < 8; w++) ss += red[w];
        red[0] = ss;
    }
    __syncthreads();
    float sum = red[0];

    float w = e / sum;
    if (w > TAU) {
        int slot = atomicAdd(&cnt, 1);
        d_sig_n[(size_t)row * PP + slot] = t;
        d_sig_w[(size_t)row * PP + slot] = w;
    }
    __syncthreads();
    if (t == 0) d_cnt[row] = cnt;
}

// ---------------- K6: sparse gated scatter ----------------
__global__ __launch_bounds__(256) void scatter_kernel(
    const float* __restrict__ x, const float* __restrict__ g_b,
    const float* __restrict__ scale, float* __restrict__ out)
{
    __shared__ float sp[DD];       // 16 KiB patch row
    __shared__ float wsum[8];
    int row = blockIdx.x;
    int b = row >> 8, p = row & 255;
    int t = threadIdx.x;
    int lane = t & 31, wid = t >> 5;

    const float* prow = d_p + (size_t)row * DD;
#pragma unroll
    for (int i = 0; i < 4; i++)
        *(float4*)(sp + (t + i * 256) * 4) = *(const float4*)(prow + (t + i * 256) * 4);
    __syncthreads();

    int cnt = d_cnt[row];
    float sc = scale[0];
    int py = p >> 4, px = p & 15;

    for (int s = 0; s < cnt; s++) {
        int   n  = d_sig_n[(size_t)row * PP + s];
        float wv = d_sig_w[(size_t)row * PP + s];
        int iy = n >> 4, ix = n & 15;
        int h = py * PH + iy, wc = px * PH + ix;
        for (int c = 0; c < CC; c++) {
            int j = c * 256 + n;
            const float* grow = d_gwT + (size_t)j * DD;
            float part = 0.f;
#pragma unroll
            for (int k = t; k < DD; k += 256)
                part += sp[k] * grow[k];
#pragma unroll
            for (int off = 16; off; off >>= 1)
                part += __shfl_down_sync(0xffffffffu, part, off);
            if (lane == 0) wsum[wid] = part;
            __syncthreads();
            if (t == 0) {
                float tot = 0.f;
#pragma unroll
                for (int ww = 0; ww < 8; ww++) tot += wsum[ww];
                size_t pix = (((size_t)b * CC + c) * HH + h) * HH + wc;
                out[pix] = x[pix] + sc * wv * (tot + g_b[j]);
            }
            __syncthreads();
        }
    }
}

// ---------------- launch ----------------
extern "C" void kernel_launch(void* const* d_in, const int* in_sizes, int n_in,
                              void* d_out, int out_size)
{
    const float* x       = (const float*)d_in[0];
    const float* theta_w = (const float*)d_in[1];
    const float* theta_b = (const float*)d_in[2];
    const float* f_w     = (const float*)d_in[3];
    const float* f_b     = (const float*)d_in[4];
    const float* g_w     = (const float*)d_in[5];
    const float* g_b     = (const float*)d_in[6];
    const float* scale   = (const float*)d_in[7];
    float* out = (float*)d_out;

    extract_kernel<<<16384, 256>>>(x, out);
    transpose_kernel<<<dim3(128, 128), dim3(32, 8)>>>(g_w);
    gemm4096<<<dim3(8, 32, 2), 256>>>(theta_w, theta_b, f_w, f_b);
    logits_kernel<<<dim3(4, 4, 16), 256>>>();
    softmax_kernel<<<ROWS, 256>>>();
    scatter_kernel<<<ROWS, 256>>>(x, g_b, scale, out);
}

// round 5
// speedup vs baseline: 1.5036x; 1.5036x over previous
#include <cuda_runtime.h>
#include <cuda_bf16.h>
#include <cstdint>

// ---------------- problem constants ----------------
#define NPAT   16
#define BB     16
#define CC     16
#define HH     256
#define PH     16
#define PP     256
#define DD     4096
#define EE     512
#define ROWS   (BB*PP)
#define TAU    1e-7f

// ---------------- GEMM tiling (mma.sync path) ----------------
#define BM     128
#define BN     128
#define BK     32
#define KSTR   40          // smem row stride in bf16 (32 data + 8 pad = 80B)

// ---------------- device scratch ----------------
__device__ float          d_p[ROWS * DD];          // 64 MiB (scatter uses fp32)
__device__ __nv_bfloat16  d_p_hi[ROWS * DD];       // 32 MiB
__device__ __nv_bfloat16  d_p_lo[ROWS * DD];       // 32 MiB
__device__ __nv_bfloat16  d_wt_hi[2 * EE * DD];    // 8 MiB  (theta_w^T, f_w^T)
__device__ __nv_bfloat16  d_wt_lo[2 * EE * DD];    // 8 MiB
__device__ float          d_gwT[DD * DD];          // 64 MiB
__device__ float          d_theta[ROWS * EE];
__device__ float          d_f[ROWS * EE];
__device__ float          d_logits[BB * PP * PP];
__device__ int            d_sig_n[ROWS * PP];
__device__ float          d_sig_w[ROWS * PP];
__device__ int            d_cnt[ROWS];

// ---------------- helpers ----------------
__device__ __forceinline__ uint32_t smem_u32(const void* p) {
    uint32_t a;
    asm("{ .reg .u64 t; cvta.to.shared.u64 t, %1; cvt.u32.u64 %0, t; }" : "=r"(a) : "l"(p));
    return a;
}
__device__ __forceinline__ void ldsm_x4(uint32_t r[4], uint32_t addr) {
    asm volatile("ldmatrix.sync.aligned.m8n8.x4.shared.b16 {%0,%1,%2,%3}, [%4];"
        : "=r"(r[0]), "=r"(r[1]), "=r"(r[2]), "=r"(r[3]) : "r"(addr));
}
__device__ __forceinline__ void mma16816(float c[4], const uint32_t a[4],
                                         uint32_t b0, uint32_t b1) {
    asm volatile("mma.sync.aligned.m16n8k16.row.col.f32.bf16.bf16.f32 "
        "{%0,%1,%2,%3}, {%4,%5,%6,%7}, {%8,%9}, {%0,%1,%2,%3};"
        : "+f"(c[0]), "+f"(c[1]), "+f"(c[2]), "+f"(c[3])
        : "r"(a[0]), "r"(a[1]), "r"(a[2]), "r"(a[3]), "r"(b0), "r"(b1));
}

// ---------------- K1: patch extract + out=x + bf16 split ----------------
__global__ __launch_bounds__(256) void extract_kernel(
    const float* __restrict__ x, float* __restrict__ out)
{
    int idx4 = blockIdx.x * 256 + threadIdx.x;
    int i = idx4 * 4;
    int w = i & 255;
    int h = (i >> 8) & 255;
    int c = (i >> 16) & 15;
    int b = i >> 20;

    float4 v = *(const float4*)(x + i);
    *(float4*)(out + i) = v;

    int py = h >> 4, iy = h & 15;
    int px = w >> 4, ix = w & 15;
    int pidx = py * NPAT + px;
    int d    = c * (PH * PH) + iy * PH + ix;
    size_t off = (size_t)(b * PP + pidx) * DD + d;
    *(float4*)(d_p + off) = v;

    float vs[4] = {v.x, v.y, v.z, v.w};
    __nv_bfloat16 hv[4], lv[4];
#pragma unroll
    for (int k = 0; k < 4; k++) {
        hv[k] = __float2bfloat16(vs[k]);
        lv[k] = __float2bfloat16(vs[k] - __bfloat162float(hv[k]));
    }
    __nv_bfloat162 h01 = __halves2bfloat162(hv[0], hv[1]);
    __nv_bfloat162 h23 = __halves2bfloat162(hv[2], hv[3]);
    __nv_bfloat162 l01 = __halves2bfloat162(lv[0], lv[1]);
    __nv_bfloat162 l23 = __halves2bfloat162(lv[2], lv[3]);
    uint2 ph_, pl_;
    ph_.x = *(uint32_t*)&h01; ph_.y = *(uint32_t*)&h23;
    pl_.x = *(uint32_t*)&l01; pl_.y = *(uint32_t*)&l23;
    *(uint2*)(d_p_hi + off) = ph_;
    *(uint2*)(d_p_lo + off) = pl_;
}

// ---------------- K2a: transpose g_w (D x D) ----------------
__global__ __launch_bounds__(256) void transpose_kernel(const float* __restrict__ gw)
{
    __shared__ float tile[32][33];
    int tx = threadIdx.x, ty = threadIdx.y;
    int x0 = blockIdx.x * 32, y0 = blockIdx.y * 32;
#pragma unroll
    for (int j = 0; j < 32; j += 8)
        tile[ty + j][tx] = gw[(size_t)(y0 + ty + j) * DD + (x0 + tx)];
    __syncthreads();
#pragma unroll
    for (int j = 0; j < 32; j += 8)
        d_gwT[(size_t)(x0 + ty + j) * DD + (y0 + tx)] = tile[tx][ty + j];
}

// ---------------- K2b: W -> W^T bf16 hi/lo for theta_w and f_w ----------------
__global__ __launch_bounds__(256) void wtprep_kernel(
    const float* __restrict__ tw, const float* __restrict__ fw)
{
    __shared__ float tile[32][33];
    int sel = blockIdx.z;
    const float* __restrict__ W = sel ? fw : tw;
    int tx = threadIdx.x, ty = threadIdx.y;        // 32 x 8
    int x0 = blockIdx.x * 32;                      // E dim
    int y0 = blockIdx.y * 32;                      // D dim
#pragma unroll
    for (int j = 0; j < 32; j += 8)
        tile[ty + j][tx] = W[(size_t)(y0 + ty + j) * EE + (x0 + tx)];
    __syncthreads();
#pragma unroll
    for (int j = 0; j < 32; j += 8) {
        float v = tile[tx][ty + j];
        __nv_bfloat16 h = __float2bfloat16(v);
        __nv_bfloat16 l = __float2bfloat16(v - __bfloat162float(h));
        size_t o = (size_t)sel * EE * DD + (size_t)(x0 + ty + j) * DD + (y0 + tx);
        d_wt_hi[o] = h;
        d_wt_lo[o] = l;
    }
}

// ---------------- K3: mma.sync GEMM  C[4096x512] = p @ W + b  (bf16 split x3) ----------------
// BM=128 BN=128 BK=32, 256 threads, warp tile 64x32 (warp grid 2m x 4n)
__global__ __launch_bounds__(256) void gemm_mma(
    const float* __restrict__ bias0, const float* __restrict__ bias1)
{
    __shared__ __nv_bfloat16 sAh[BM * KSTR];
    __shared__ __nv_bfloat16 sAl[BM * KSTR];
    __shared__ __nv_bfloat16 sBh[BN * KSTR];
    __shared__ __nv_bfloat16 sBl[BN * KSTR];

    int sel = blockIdx.z;
    int m0 = blockIdx.y * BM;
    int n0 = blockIdx.x * BN;
    const float* __restrict__ bias = sel ? bias1 : bias0;
    float* C = sel ? d_f : d_theta;

    const __nv_bfloat16* gAh = d_p_hi + (size_t)m0 * DD;
    const __nv_bfloat16* gAl = d_p_lo + (size_t)m0 * DD;
    const __nv_bfloat16* gBh = d_wt_hi + (size_t)sel * EE * DD + (size_t)n0 * DD;
    const __nv_bfloat16* gBl = d_wt_lo + (size_t)sel * EE * DD + (size_t)n0 * DD;

    int t = threadIdx.x;
    int warp = t >> 5, lane = t & 31;
    int wm = warp & 1;             // 0..1, 64 rows each
    int wn = warp >> 1;            // 0..3, 32 cols each

    // ldmatrix lane addressing: row = lane&15, col byte = (lane>>4)*16
    int lrow = lane & 15;
    int lcolB = (lane >> 4) * 16;  // bytes (8 bf16)

    uint32_t uAh = smem_u32(sAh), uAl = smem_u32(sAl);
    uint32_t uBh = smem_u32(sBh), uBl = smem_u32(sBl);

    float acc[4][4][4];            // [mblk][n8frag][reg]
#pragma unroll
    for (int i = 0; i < 4; i++)
#pragma unroll
        for (int j = 0; j < 4; j++)
#pragma unroll
            for (int r = 0; r < 4; r++) acc[i][j][r] = 0.f;

    // global->smem mapping: thread t loads row = t>>1, 16 bf16 at (t&1)*16
    int grow = t >> 1;
    int ghalf = (t & 1) * 16;
    uint32_t soff = (uint32_t)(grow * KSTR + ghalf) * 2;   // byte offset in smem tile

    for (int k0 = 0; k0 < DD; k0 += BK) {
        __syncthreads();
        {
            const uint4* a0 = (const uint4*)(gAh + (size_t)grow * DD + k0 + ghalf);
            const uint4* a1 = (const uint4*)(gAl + (size_t)grow * DD + k0 + ghalf);
            const uint4* b0 = (const uint4*)(gBh + (size_t)grow * DD + k0 + ghalf);
            const uint4* b1 = (const uint4*)(gBl + (size_t)grow * DD + k0 + ghalf);
            uint4* dAh = (uint4*)((char*)sAh + soff);
            uint4* dAl = (uint4*)((char*)sAl + soff);
            uint4* dBh = (uint4*)((char*)sBh + soff);
            uint4* dBl = (uint4*)((char*)sBl + soff);
            dAh[0] = a0[0]; dAh[1] = a0[1];
            dAl[0] = a1[0]; dAl[1] = a1[1];
            dBh[0] = b0[0]; dBh[1] = b0[1];
            dBl[0] = b1[0]; dBl[1] = b1[1];
        }
        __syncthreads();

#pragma unroll
        for (int ks = 0; ks < 2; ks++) {
            int kbyte = ks * 32;   // 16 bf16

            uint32_t a[4][4];      // Ah frags for 4 m16 blocks
            uint32_t bh[2][4], bl[2][4];

#pragma unroll
            for (int mb = 0; mb < 4; mb++) {
                uint32_t ad = uAh + (uint32_t)((wm * 64 + mb * 16 + lrow) * KSTR * 2)
                            + kbyte + lcolB;
                ldsm_x4(a[mb], ad);
            }
#pragma unroll
            for (int nb = 0; nb < 2; nb++) {
                uint32_t bd = uBh + (uint32_t)((wn * 32 + nb * 16 + lrow) * KSTR * 2)
                            + kbyte + lcolB;
                ldsm_x4(bh[nb], bd);
                uint32_t bd2 = uBl + (uint32_t)((wn * 32 + nb * 16 + lrow) * KSTR * 2)
                             + kbyte + lcolB;
                ldsm_x4(bl[nb], bd2);
            }

            // pass 1: Ah * Bh, pass 2: Ah * Bl
#pragma unroll
            for (int mb = 0; mb < 4; mb++)
#pragma unroll
                for (int j = 0; j < 4; j++) {
                    mma16816(acc[mb][j], a[mb], bh[j >> 1][j & 1], bh[j >> 1][2 + (j & 1)]);
                    mma16816(acc[mb][j], a[mb], bl[j >> 1][j & 1], bl[j >> 1][2 + (j & 1)]);
                }

            // pass 3: Al * Bh (reload a with lo)
#pragma unroll
            for (int mb = 0; mb < 4; mb++) {
                uint32_t ad = uAl + (uint32_t)((wm * 64 + mb * 16 + lrow) * KSTR * 2)
                            + kbyte + lcolB;
                ldsm_x4(a[mb], ad);
            }
#pragma unroll
            for (int mb = 0; mb < 4; mb++)
#pragma unroll
                for (int j = 0; j < 4; j++)
                    mma16816(acc[mb][j], a[mb], bh[j >> 1][j & 1], bh[j >> 1][2 + (j & 1)]);
        }
    }

    // epilogue: acc layout: c0,c1 = row g, cols 2t,2t+1 ; c2,c3 = row g+8
    int g = lane >> 2, tg = lane & 3;
#pragma unroll
    for (int mb = 0; mb < 4; mb++) {
#pragma unroll
        for (int j = 0; j < 4; j++) {
            int col = n0 + wn * 32 + j * 8 + tg * 2;
            float2 bv = *(const float2*)(bias + col);
            int r0 = m0 + wm * 64 + mb * 16 + g;
            float2 o0 = make_float2(acc[mb][j][0] + bv.x, acc[mb][j][1] + bv.y);
            float2 o1 = make_float2(acc[mb][j][2] + bv.x, acc[mb][j][3] + bv.y);
            *(float2*)(C + (size_t)r0 * EE + col)       = o0;
            *(float2*)(C + (size_t)(r0 + 8) * EE + col) = o1;
        }
    }
}

// ---------------- K4: logits  L[b] = theta[b] @ f[b]^T ----------------
__global__ __launch_bounds__(256) void logits_kernel()
{
    __shared__ float As[16][64];
    __shared__ float Bs[16][64];
    int b  = blockIdx.z;
    int t  = threadIdx.x;
    int tx = t & 15, ty = t >> 4;
    int p0 = blockIdx.y * 64, q0 = blockIdx.x * 64;

    const float* A  = d_theta + (size_t)b * PP * EE;
    const float* Bm = d_f     + (size_t)b * PP * EE;

    int ar = t >> 2;
    int ak = (t & 3) * 4;

    float acc[4][4];
#pragma unroll
    for (int i = 0; i < 4; i++)
#pragma unroll
        for (int j = 0; j < 4; j++) acc[i][j] = 0.f;

    for (int e0 = 0; e0 < EE; e0 += 16) {
        float4 av = *(const float4*)(A  + (size_t)(p0 + ar) * EE + e0 + ak);
        As[ak + 0][ar] = av.x; As[ak + 1][ar] = av.y;
        As[ak + 2][ar] = av.z; As[ak + 3][ar] = av.w;
        float4 bv = *(const float4*)(Bm + (size_t)(q0 + ar) * EE + e0 + ak);
        Bs[ak + 0][ar] = bv.x; Bs[ak + 1][ar] = bv.y;
        Bs[ak + 2][ar] = bv.z; Bs[ak + 3][ar] = bv.w;
        __syncthreads();
#pragma unroll
        for (int kk = 0; kk < 16; kk++) {
            float4 a  = *(const float4*)&As[kk][ty * 4];
            float4 b2 = *(const float4*)&Bs[kk][tx * 4];
            float ra[4] = {a.x, a.y, a.z, a.w};
            float rb[4] = {b2.x, b2.y, b2.z, b2.w};
#pragma unroll
            for (int i = 0; i < 4; i++)
#pragma unroll
                for (int j = 0; j < 4; j++) acc[i][j] += ra[i] * rb[j];
        }
        __syncthreads();
    }
#pragma unroll
    for (int i = 0; i < 4; i++) {
        float4 o = make_float4(acc[i][0], acc[i][1], acc[i][2], acc[i][3]);
        *(float4*)(d_logits + (size_t)b * PP * PP + (size_t)(p0 + ty * 4 + i) * PP
                   + q0 + tx * 4) = o;
    }
}

// ---------------- K5: softmax + tau-compaction ----------------
__global__ __launch_bounds__(256) void softmax_kernel()
{
    __shared__ float red[8];
    __shared__ int   cnt;
    int row = blockIdx.x;
    int t = threadIdx.x;
    int lane = t & 31, wid = t >> 5;

    float l = d_logits[(size_t)row * PP + t];

    float m = l;
#pragma unroll
    for (int off = 16; off; off >>= 1)
        m = fmaxf(m, __shfl_down_sync(0xffffffffu, m, off));
    if (lane == 0) red[wid] = m;
    __syncthreads();
    if (t == 0) {
        float mm = red[0];
#pragma unroll
        for (int w = 1; w < 8; w++) mm = fmaxf(mm, red[w]);
        red[0] = mm;
        cnt = 0;
    }
    __syncthreads();
    float mx = red[0];
    __syncthreads();

    float e = expf(l - mx);
    float s = e;
#pragma unroll
    for (int off = 16; off; off >>= 1)
        s += __shfl_down_sync(0xffffffffu, s, off);
    if (lane == 0) red[wid] = s;
    __syncthreads();
    if (t == 0) {
        float ss = 0.f;
#pragma unroll
        for (int w = 0; w < 8; w++) ss += red[w];
        red[0] = ss;
    }
    __syncthreads();
    float sum = red[0];

    float w = e / sum;
    if (w > TAU) {
        int slot = atomicAdd(&cnt, 1);
        d_sig_n[(size_t)row * PP + slot] = t;
        d_sig_w[(size_t)row * PP + slot] = w;
    }
    __syncthreads();
    if (t == 0) d_cnt[row] = cnt;
}

// ---------------- K6: sparse gated scatter ----------------
__global__ __launch_bounds__(256) void scatter_kernel(
    const float* __restrict__ x, const float* __restrict__ g_b,
    const float* __restrict__ scale, float* __restrict__ out)
{
    __shared__ float sp[DD];
    __shared__ float wsum[8];
    int row = blockIdx.x;
    int b = row >> 8, p = row & 255;
    int t = threadIdx.x;
    int lane = t & 31, wid = t >> 5;

    const float* prow = d_p + (size_t)row * DD;
#pragma unroll
    for (int i = 0; i < 4; i++)
        *(float4*)(sp + (t + i * 256) * 4) = *(const float4*)(prow + (t + i * 256) * 4);
    __syncthreads();

    int cnt = d_cnt[row];
    float sc = scale[0];
    int py = p >> 4, px = p & 15;

    for (int s = 0; s < cnt; s++) {
        int   n  = d_sig_n[(size_t)row * PP + s];
        float wv = d_sig_w[(size_t)row * PP + s];
        int iy = n >> 4, ix = n & 15;
        int h = py * PH + iy, wc = px * PH + ix;
        for (int c = 0; c < CC; c++) {
            int j = c * 256 + n;
            const float* grow = d_gwT + (size_t)j * DD;
            float part = 0.f;
#pragma unroll
            for (int k = t; k < DD; k += 256)
                part += sp[k] * grow[k];
#pragma unroll
            for (int off = 16; off; off >>= 1)
                part += __shfl_down_sync(0xffffffffu, part, off);
            if (lane == 0) wsum[wid] = part;
            __syncthreads();
            if (t == 0) {
                float tot = 0.f;
#pragma unroll
                for (int ww = 0; ww < 8; ww++) tot += wsum[ww];
                size_t pix = (((size_t)b * CC + c) * HH + h) * HH + wc;
                out[pix] = x[pix] + sc * wv * (tot + g_b[j]);
            }
            __syncthreads();
        }
    }
}

// ---------------- launch ----------------
extern "C" void kernel_launch(void* const* d_in, const int* in_sizes, int n_in,
                              void* d_out, int out_size)
{
    const float* x       = (const float*)d_in[0];
    const float* theta_w = (const float*)d_in[1];
    const float* theta_b = (const float*)d_in[2];
    const float* f_w     = (const float*)d_in[3];
    const float* f_b     = (const float*)d_in[4];
    const float* g_w     = (const float*)d_in[5];
    const float* g_b     = (const float*)d_in[6];
    const float* scale   = (const float*)d_in[7];
    float* out = (float*)d_out;

    extract_kernel<<<16384, 256>>>(x, out);
    transpose_kernel<<<dim3(128, 128), dim3(32, 8)>>>(g_w);
    wtprep_kernel<<<dim3(16, 128, 2), dim3(32, 8)>>>(theta_w, f_w);
    gemm_mma<<<dim3(4, 32, 2), 256>>>(theta_b, f_b);
    logits_kernel<<<dim3(4, 4, 16), 256>>>();
    softmax_kernel<<<ROWS, 256>>>();
    scatter_kernel<<<ROWS, 256>>>(x, g_b, scale, out);
}

// round 13
// speedup vs baseline: 2.1399x; 1.4231x over previous
#include <cuda_runtime.h>
#include <cuda_bf16.h>
#include <cstdint>

// ---------------- problem constants ----------------
#define NPAT   16
#define BB     16
#define CC     16
#define HH     256
#define PH     16
#define PP     256
#define DD     4096
#define EE     512
#define ROWS   (BB*PP)
#define TAU    1e-7f

// ---------------- GEMM tiling (mma.sync + cp.async path) ----------------
#define BM     128
#define BN     128
#define BK     32
#define KSTR   40          // smem row stride in bf16 (32 data + 8 pad = 80B, ldsm conflict-free)
#define TILEW  (BM*KSTR)   // bf16 per tile buffer
#define NIT    (DD/BK)     // 128 k-tiles
#define GEMM_SMEM (2*4*TILEW*2)   // 2 stages x 4 tiles x 10240B = 81920B

// ---------------- device scratch ----------------
__device__ float          d_p[ROWS * DD];          // 64 MiB (scatter uses fp32)
__device__ __nv_bfloat16  d_p_hi[ROWS * DD];       // 32 MiB
__device__ __nv_bfloat16  d_p_lo[ROWS * DD];       // 32 MiB
__device__ __nv_bfloat16  d_wt_hi[2 * EE * DD];    // 8 MiB  (theta_w^T, f_w^T)
__device__ __nv_bfloat16  d_wt_lo[2 * EE * DD];    // 8 MiB
__device__ float          d_gwT[DD * DD];          // 64 MiB
__device__ float          d_theta[ROWS * EE];
__device__ float          d_f[ROWS * EE];
__device__ float          d_logits[BB * PP * PP];
__device__ int            d_sig_n[ROWS * PP];
__device__ float          d_sig_w[ROWS * PP];
__device__ int            d_cnt[ROWS];

// ---------------- helpers ----------------
__device__ __forceinline__ uint32_t smem_u32(const void* p) {
    uint32_t a;
    asm("{ .reg .u64 t; cvta.to.shared.u64 t, %1; cvt.u32.u64 %0, t; }" : "=r"(a) : "l"(p));
    return a;
}
__device__ __forceinline__ void ldsm_x4(uint32_t r[4], uint32_t addr) {
    asm volatile("ldmatrix.sync.aligned.m8n8.x4.shared.b16 {%0,%1,%2,%3}, [%4];"
        : "=r"(r[0]), "=r"(r[1]), "=r"(r[2]), "=r"(r[3]) : "r"(addr));
}
__device__ __forceinline__ void mma16816(float c[4], const uint32_t a[4],
                                         uint32_t b0, uint32_t b1) {
    asm volatile("mma.sync.aligned.m16n8k16.row.col.f32.bf16.bf16.f32 "
        "{%0,%1,%2,%3}, {%4,%5,%6,%7}, {%8,%9}, {%0,%1,%2,%3};"
        : "+f"(c[0]), "+f"(c[1]), "+f"(c[2]), "+f"(c[3])
        : "r"(a[0]), "r"(a[1]), "r"(a[2]), "r"(a[3]), "r"(b0), "r"(b1));
}
__device__ __forceinline__ void cp16(uint32_t dst, const void* src) {
    asm volatile("cp.async.cg.shared.global [%0], [%1], 16;" :: "r"(dst), "l"(src));
}
#define CP_COMMIT() asm volatile("cp.async.commit_group;" ::: "memory")
#define CP_WAIT0()  asm volatile("cp.async.wait_group 0;" ::: "memory")

// ---------------- K1: patch extract + out=x + bf16 split ----------------
__global__ __launch_bounds__(256) void extract_kernel(
    const float* __restrict__ x, float* __restrict__ out)
{
    int idx4 = blockIdx.x * 256 + threadIdx.x;
    int i = idx4 * 4;
    int w = i & 255;
    int h = (i >> 8) & 255;
    int c = (i >> 16) & 15;
    int b = i >> 20;

    float4 v = *(const float4*)(x + i);
    *(float4*)(out + i) = v;

    int py = h >> 4, iy = h & 15;
    int px = w >> 4, ix = w & 15;
    int pidx = py * NPAT + px;
    int d    = c * (PH * PH) + iy * PH + ix;
    size_t off = (size_t)(b * PP + pidx) * DD + d;
    *(float4*)(d_p + off) = v;

    float vs[4] = {v.x, v.y, v.z, v.w};
    __nv_bfloat16 hv[4], lv[4];
#pragma unroll
    for (int k = 0; k < 4; k++) {
        hv[k] = __float2bfloat16(vs[k]);
        lv[k] = __float2bfloat16(vs[k] - __bfloat162float(hv[k]));
    }
    __nv_bfloat162 h01 = __halves2bfloat162(hv[0], hv[1]);
    __nv_bfloat162 h23 = __halves2bfloat162(hv[2], hv[3]);
    __nv_bfloat162 l01 = __halves2bfloat162(lv[0], lv[1]);
    __nv_bfloat162 l23 = __halves2bfloat162(lv[2], lv[3]);
    uint2 ph_, pl_;
    ph_.x = *(uint32_t*)&h01; ph_.y = *(uint32_t*)&h23;
    pl_.x = *(uint32_t*)&l01; pl_.y = *(uint32_t*)&l23;
    *(uint2*)(d_p_hi + off) = ph_;
    *(uint2*)(d_p_lo + off) = pl_;
}

// ---------------- K2a: transpose g_w (D x D) ----------------
__global__ __launch_bounds__(256) void transpose_kernel(const float* __restrict__ gw)
{
    __shared__ float tile[32][33];
    int tx = threadIdx.x, ty = threadIdx.y;
    int x0 = blockIdx.x * 32, y0 = blockIdx.y * 32;
#pragma unroll
    for (int j = 0; j < 32; j += 8)
        tile[ty + j][tx] = gw[(size_t)(y0 + ty + j) * DD + (x0 + tx)];
    __syncthreads();
#pragma unroll
    for (int j = 0; j < 32; j += 8)
        d_gwT[(size_t)(x0 + ty + j) * DD + (y0 + tx)] = tile[tx][ty + j];
}

// ---------------- K2b: W -> W^T bf16 hi/lo for theta_w and f_w ----------------
__global__ __launch_bounds__(256) void wtprep_kernel(
    const float* __restrict__ tw, const float* __restrict__ fw)
{
    __shared__ float tile[32][33];
    int sel = blockIdx.z;
    const float* __restrict__ W = sel ? fw : tw;
    int tx = threadIdx.x, ty = threadIdx.y;        // 32 x 8
    int x0 = blockIdx.x * 32;                      // E dim
    int y0 = blockIdx.y * 32;                      // D dim
#pragma unroll
    for (int j = 0; j < 32; j += 8)
        tile[ty + j][tx] = W[(size_t)(y0 + ty + j) * EE + (x0 + tx)];
    __syncthreads();
#pragma unroll
    for (int j = 0; j < 32; j += 8) {
        float v = tile[tx][ty + j];
        __nv_bfloat16 h = __float2bfloat16(v);
        __nv_bfloat16 l = __float2bfloat16(v - __bfloat162float(h));
        size_t o = (size_t)sel * EE * DD + (size_t)(x0 + ty + j) * DD + (y0 + tx);
        d_wt_hi[o] = h;
        d_wt_lo[o] = l;
    }
}

// ---------------- K3: mma.sync GEMM, cp.async 2-stage pipeline ----------------
__global__ __launch_bounds__(256) void gemm_mma(
    const float* __restrict__ bias0, const float* __restrict__ bias1)
{
    extern __shared__ __nv_bfloat16 sm[];
    uint32_t sbase = smem_u32(sm);

    int sel = blockIdx.z;
    int m0 = blockIdx.y * BM;
    int n0 = blockIdx.x * BN;
    const float* __restrict__ bias = sel ? bias1 : bias0;
    float* C = sel ? d_f : d_theta;

    const __nv_bfloat16* gsrc[4] = {
        d_p_hi + (size_t)m0 * DD,
        d_p_lo + (size_t)m0 * DD,
        d_wt_hi + (size_t)sel * EE * DD + (size_t)n0 * DD,
        d_wt_lo + (size_t)sel * EE * DD + (size_t)n0 * DD
    };

    int t = threadIdx.x;
    int warp = t >> 5, lane = t & 31;
    int wm = warp & 1;             // 0..1, 64 rows each
    int wn = warp >> 1;            // 0..3, 32 cols each
    int lrow = lane & 15;
    int lcolB = (lane >> 4) * 16;  // bytes

    // global->smem mapping: thread t loads row = t>>1, 16 bf16 at (t&1)*16
    int grow = t >> 1;
    int ghalf = (t & 1) * 16;
    uint32_t sdst0 = (uint32_t)(grow * KSTR + ghalf) * 2;

    float acc[4][4][4];
#pragma unroll
    for (int i = 0; i < 4; i++)
#pragma unroll
        for (int j = 0; j < 4; j++)
#pragma unroll
            for (int r = 0; r < 4; r++) acc[i][j][r] = 0.f;

    // issue loads for k-tile `kt` into stage `st`
    auto issue = [&](int st, int kt) {
        uint32_t stoff = (uint32_t)(st * 4 * TILEW) * 2;
#pragma unroll
        for (int tile = 0; tile < 4; tile++) {
            const __nv_bfloat16* src = gsrc[tile] + (size_t)grow * DD + kt * BK + ghalf;
            uint32_t dst = sbase + stoff + (uint32_t)(tile * TILEW) * 2 + sdst0;
            cp16(dst, src);
            cp16(dst + 16, (const char*)src + 16);
        }
        CP_COMMIT();
    };

    issue(0, 0);

    for (int it = 0; it < NIT; it++) {
        int st = it & 1;
        CP_WAIT0();
        __syncthreads();                 // stage st ready; all compute on st^1 done
        if (it + 1 < NIT) issue(st ^ 1, it + 1);

        uint32_t ubase = sbase + (uint32_t)(st * 4 * TILEW) * 2;
        uint32_t uAh = ubase;
        uint32_t uAl = ubase + (uint32_t)TILEW * 2;
        uint32_t uBh = ubase + (uint32_t)(2 * TILEW) * 2;
        uint32_t uBl = ubase + (uint32_t)(3 * TILEW) * 2;

#pragma unroll
        for (int ks = 0; ks < 2; ks++) {
            int kbyte = ks * 32;

            uint32_t a[4][4];
            uint32_t bh[2][4], bl[2][4];

#pragma unroll
            for (int mb = 0; mb < 4; mb++) {
                uint32_t ad = uAh + (uint32_t)((wm * 64 + mb * 16 + lrow) * KSTR * 2)
                            + kbyte + lcolB;
                ldsm_x4(a[mb], ad);
            }
#pragma unroll
            for (int nb = 0; nb < 2; nb++) {
                uint32_t bd = uBh + (uint32_t)((wn * 32 + nb * 16 + lrow) * KSTR * 2)
                            + kbyte + lcolB;
                ldsm_x4(bh[nb], bd);
                uint32_t bd2 = uBl + (uint32_t)((wn * 32 + nb * 16 + lrow) * KSTR * 2)
                             + kbyte + lcolB;
                ldsm_x4(bl[nb], bd2);
            }

            // pass 1: Ah*Bh, pass 2: Ah*Bl
#pragma unroll
            for (int mb = 0; mb < 4; mb++)
#pragma unroll
                for (int j = 0; j < 4; j++) {
                    mma16816(acc[mb][j], a[mb], bh[j >> 1][j & 1], bh[j >> 1][2 + (j & 1)]);
                    mma16816(acc[mb][j], a[mb], bl[j >> 1][j & 1], bl[j >> 1][2 + (j & 1)]);
                }

            // pass 3: Al*Bh
#pragma unroll
            for (int mb = 0; mb < 4; mb++) {
                uint32_t ad = uAl + (uint32_t)((wm * 64 + mb * 16 + lrow) * KSTR * 2)
                            + kbyte + lcolB;
                ldsm_x4(a[mb], ad);
            }
#pragma unroll
            for (int mb = 0; mb < 4; mb++)
#pragma unroll
                for (int j = 0; j < 4; j++)
                    mma16816(acc[mb][j], a[mb], bh[j >> 1][j & 1], bh[j >> 1][2 + (j & 1)]);
        }
        __syncthreads();                 // compute on st done before it+1 overwrites st
    }

    // epilogue
    int g = lane >> 2, tg = lane & 3;
#pragma unroll
    for (int mb = 0; mb < 4; mb++) {
#pragma unroll
        for (int j = 0; j < 4; j++) {
            int col = n0 + wn * 32 + j * 8 + tg * 2;
            float2 bv = *(const float2*)(bias + col);
            int r0 = m0 + wm * 64 + mb * 16 + g;
            float2 o0 = make_float2(acc[mb][j][0] + bv.x, acc[mb][j][1] + bv.y);
            float2 o1 = make_float2(acc[mb][j][2] + bv.x, acc[mb][j][3] + bv.y);
            *(float2*)(C + (size_t)r0 * EE + col)       = o0;
            *(float2*)(C + (size_t)(r0 + 8) * EE + col) = o1;
        }
    }
}

// ---------------- K4: logits  L[b] = theta[b] @ f[b]^T ----------------
__global__ __launch_bounds__(256) void logits_kernel()
{
    __shared__ float As[16][64];
    __shared__ float Bs[16][64];
    int b  = blockIdx.z;
    int t  = threadIdx.x;
    int tx = t & 15, ty = t >> 4;
    int p0 = blockIdx.y * 64, q0 = blockIdx.x * 64;

    const float* A  = d_theta + (size_t)b * PP * EE;
    const float* Bm = d_f     + (size_t)b * PP * EE;

    int ar = t >> 2;
    int ak = (t & 3) * 4;

    float acc[4][4];
#pragma unroll
    for (int i = 0; i < 4; i++)
#pragma unroll
        for (int j = 0; j < 4; j++) acc[i][j] = 0.f;

    for (int e0 = 0; e0 < EE; e0 += 16) {
        float4 av = *(const float4*)(A  + (size_t)(p0 + ar) * EE + e0 + ak);
        As[ak + 0][ar] = av.x; As[ak + 1][ar] = av.y;
        As[ak + 2][ar] = av.z; As[ak + 3][ar] = av.w;
        float4 bv = *(const float4*)(Bm + (size_t)(q0 + ar) * EE + e0 + ak);
        Bs[ak + 0][ar] = bv.x; Bs[ak + 1][ar] = bv.y;
        Bs[ak + 2][ar] = bv.z; Bs[ak + 3][ar] = bv.w;
        __syncthreads();
#pragma unroll
        for (int kk = 0; kk < 16; kk++) {
            float4 a  = *(const float4*)&As[kk][ty * 4];
            float4 b2 = *(const float4*)&Bs[kk][tx * 4];
            float ra[4] = {a.x, a.y, a.z, a.w};
            float rb[4] = {b2.x, b2.y, b2.z, b2.w};
#pragma unroll
            for (int i = 0; i < 4; i++)
#pragma unroll
                for (int j = 0; j < 4; j++) acc[i][j] += ra[i] * rb[j];
        }
        __syncthreads();
    }
#pragma unroll
    for (int i = 0; i < 4; i++) {
        float4 o = make_float4(acc[i][0], acc[i][1], acc[i][2], acc[i][3]);
        *(float4*)(d_logits + (size_t)b * PP * PP + (size_t)(p0 + ty * 4 + i) * PP
                   + q0 + tx * 4) = o;
    }
}

// ---------------- K5: softmax + tau-compaction ----------------
__global__ __launch_bounds__(256) void softmax_kernel()
{
    __shared__ float red[8];
    __shared__ int   cnt;
    int row = blockIdx.x;
    int t = threadIdx.x;
    int lane = t & 31, wid = t >> 5;

    float l = d_logits[(size_t)row * PP + t];

    float m = l;
#pragma unroll
    for (int off = 16; off; off >>= 1)
        m = fmaxf(m, __shfl_down_sync(0xffffffffu, m, off));
    if (lane == 0) red[wid] = m;
    __syncthreads();
    if (t == 0) {
        float mm = red[0];
#pragma unroll
        for (int w = 1; w < 8; w++) mm = fmaxf(mm, red[w]);
        red[0] = mm;
        cnt = 0;
    }
    __syncthreads();
    float mx = red[0];
    __syncthreads();

    float e = expf(l - mx);
    float s = e;
#pragma unroll
    for (int off = 16; off; off >>= 1)
        s += __shfl_down_sync(0xffffffffu, s, off);
    if (lane == 0) red[wid] = s;
    __syncthreads();
    if (t == 0) {
        float ss = 0.f;
#pragma unroll
        for (int w = 0; w < 8; w++) ss += red[w];
        red[0] = ss;
    }
    __syncthreads();
    float sum = red[0];

    float w = e / sum;
    if (w > TAU) {
        int slot = atomicAdd(&cnt, 1);
        d_sig_n[(size_t)row * PP + slot] = t;
        d_sig_w[(size_t)row * PP + slot] = w;
    }
    __syncthreads();
    if (t == 0) d_cnt[row] = cnt;
}

// ---------------- K6: sparse gated scatter, warp-per-channel ----------------
__global__ __launch_bounds__(256) void scatter_kernel(
    const float* __restrict__ x, const float* __restrict__ g_b,
    const float* __restrict__ scale, float* __restrict__ out)
{
    __shared__ float sp[DD];
    int row = blockIdx.x;
    int b = row >> 8, p = row & 255;
    int t = threadIdx.x;
    int lane = t & 31, wid = t >> 5;

    const float* prow = d_p + (size_t)row * DD;
#pragma unroll
    for (int i = 0; i < 4; i++)
        *(float4*)(sp + (t + i * 256) * 4) = *(const float4*)(prow + (t + i * 256) * 4);
    __syncthreads();

    int cnt = d_cnt[row];
    float sc = scale[0];
    int py = p >> 4, px = p & 15;
    const float4* sp4 = (const float4*)sp;

    for (int s = 0; s < cnt; s++) {
        int   n  = d_sig_n[(size_t)row * PP + s];
        float wv = d_sig_w[(size_t)row * PP + s];
        int iy = n >> 4, ix = n & 15;
        int h = py * PH + iy, wc = px * PH + ix;
        // 8 warps cover 16 channels, no block barriers
        for (int c = wid; c < CC; c += 8) {
            int j = c * 256 + n;
            const float4* grow4 = (const float4*)(d_gwT + (size_t)j * DD);
            float part = 0.f;
#pragma unroll 8
            for (int k4 = lane; k4 < DD / 4; k4 += 32) {
                float4 g = grow4[k4];
                float4 s4 = sp4[k4];
                part += s4.x * g.x + s4.y * g.y + s4.z * g.z + s4.w * g.w;
            }
#pragma unroll
            for (int off = 16; off; off >>= 1)
                part += __shfl_down_sync(0xffffffffu, part, off);
            if (lane == 0) {
                size_t pix = (((size_t)b * CC + c) * HH + h) * HH + wc;
                out[pix] = x[pix] + sc * wv * (part + g_b[j]);
            }
        }
    }
}

// ---------------- launch ----------------
extern "C" void kernel_launch(void* const* d_in, const int* in_sizes, int n_in,
                              void* d_out, int out_size)
{
    const float* x       = (const float*)d_in[0];
    const float* theta_w = (const float*)d_in[1];
    const float* theta_b = (const float*)d_in[2];
    const float* f_w     = (const float*)d_in[3];
    const float* f_b     = (const float*)d_in[4];
    const float* g_w     = (const float*)d_in[5];
    const float* g_b     = (const float*)d_in[6];
    const float* scale   = (const float*)d_in[7];
    float* out = (float*)d_out;

    extract_kernel<<<16384, 256>>>(x, out);
    transpose_kernel<<<dim3(128, 128), dim3(32, 8)>>>(g_w);
    wtprep_kernel<<<dim3(16, 128, 2), dim3(32, 8)>>>(theta_w, f_w);

    cudaFuncSetAttribute(gemm_mma, cudaFuncAttributeMaxDynamicSharedMemorySize, GEMM_SMEM);
    gemm_mma<<<dim3(4, 32, 2), 256, GEMM_SMEM>>>(theta_b, f_b);

    logits_kernel<<<dim3(4, 4, 16), 256>>>();
    softmax_kernel<<<ROWS, 256>>>();
    scatter_kernel<<<ROWS, 256>>>(x, g_b, scale, out);
}